// round 17
// baseline (speedup 1.0000x reference)
#include <cuda_runtime.h>
#include <cuda_fp16.h>
#include <cstdint>

// ---------------------------------------------------------------------------
// KAN-Mixer fused kernel (round 11): spline region on INT8 mma.sync m16n8k32
// (2x MACs/instruction vs f16 k16 on the dispatch-capped fallback tensor path),
// base region on fp16 mma with fp32 accum. Per-tensor symmetric weight quant
// with exact absmax reduction; features quantized to [0,127].
// MTILE=64, 2 CTAs/SM, cp.async double-buffered weights, h fp16 in smem.
// ---------------------------------------------------------------------------

#define PP   196
#define CC   768
#define HSZ  384

#define NT1  48            // n8 tiles layer1
#define NC1  56            // chunks of 32 k   (spline: 0..48, base: 49..55)
#define NT2  25            // n8 tiles layer2 (200 = 196 padded to 8)
#define NC2  108           // (spline: 0..95, base: 96..107)

#define MTILE 64
#define NTH  256
#define L2E  1.4426950408889634f

#define W1ELEMS (112u * 48u * 64u)     // 344064 uints (fp16 frags, full K)
#define W2ELEMS (216u * 25u * 64u)     // 345600 uints
#define Q1ELEMS (49u * 48u * 64u)      // 150528 uints (s8 frags, spline K only)
#define Q2ELEMS (96u * 25u * 64u)      // 153600 uints
#define L2CHUNK (25u * 64u * 2u)       // 3200 uints per fp16 32-k chunk

__device__ unsigned g_W1[W1ELEMS];
__device__ unsigned g_W2[W2ELEMS];
__device__ unsigned g_W1q[Q1ELEMS];
__device__ unsigned g_W2q[Q2ELEMS];
__device__ int g_absmax[2];            // float bits of max|w| (zero-init)

// ----------------------------- helpers --------------------------------------
static __device__ __forceinline__ float ex2f(float z) {
    float r; asm("ex2.approx.ftz.f32 %0, %1;" : "=f"(r) : "f"(z)); return r;
}
static __device__ __forceinline__ float rcpf(float z) {
    float r; asm("rcp.approx.ftz.f32 %0, %1;" : "=f"(r) : "f"(z)); return r;
}
static __device__ __forceinline__ float basis_feat(float v, int q) {
    float u = (v + 1.0f) * 3.5f - (float)q;
    float z = fmaxf(-u * u * L2E, -126.0f);
    return ex2f(z);
}
static __device__ __forceinline__ float silu_feat(float v) {
    float z = fminf(fmaxf(-v * L2E, -126.0f), 126.0f);
    return v * rcpf(1.0f + ex2f(z));
}
static __device__ __forceinline__ unsigned h2pack(float a, float b) {
    __half2 h = __floats2half2_rn(a, b);
    return *reinterpret_cast<unsigned*>(&h);
}
static __device__ __forceinline__ unsigned pack4(int a, int b, int c, int d) {
    return (unsigned)(a & 255) | ((unsigned)(b & 255) << 8) |
           ((unsigned)(c & 255) << 16) | ((unsigned)(d & 255) << 24);
}
// fp32-accumulator fp16 MMA (base region)
static __device__ __forceinline__ void mma16(float* d, const uint4& A, const uint2& B) {
    asm volatile(
        "mma.sync.aligned.m16n8k16.row.col.f32.f16.f16.f32 "
        "{%0,%1,%2,%3}, {%4,%5,%6,%7}, {%8,%9}, {%0,%1,%2,%3};"
        : "+f"(d[0]), "+f"(d[1]), "+f"(d[2]), "+f"(d[3])
        : "r"(A.x), "r"(A.y), "r"(A.z), "r"(A.w), "r"(B.x), "r"(B.y));
}
// s8 MMA k32 (spline region)
static __device__ __forceinline__ void mmas8(int* d, const uint4& A, const uint2& B) {
    asm volatile(
        "mma.sync.aligned.m16n8k32.row.col.s32.s8.s8.s32 "
        "{%0,%1,%2,%3}, {%4,%5,%6,%7}, {%8,%9}, {%0,%1,%2,%3};"
        : "+r"(d[0]), "+r"(d[1]), "+r"(d[2]), "+r"(d[3])
        : "r"(A.x), "r"(A.y), "r"(A.z), "r"(A.w), "r"(B.x), "r"(B.y));
}
static __device__ __forceinline__ void cpasync16(void* dst, const void* src) {
    unsigned s = (unsigned)__cvta_generic_to_shared(dst);
    asm volatile("cp.async.cg.shared.global [%0], [%1], 16;" :: "r"(s), "l"(src));
}
static __device__ __forceinline__ void cp_commit() {
    asm volatile("cp.async.commit_group;" ::: "memory");
}
static __device__ __forceinline__ void cp_wait0() {
    asm volatile("cp.async.wait_group 0;" ::: "memory");
}

// --------------------------- absmax reduction --------------------------------
__global__ void absmax_k(const float* __restrict__ sw1, const float* __restrict__ sw2) {
    const int N = 602112;     // 1568*384 == 3072*196
    float m1 = 0.0f, m2 = 0.0f;
    for (int i = blockIdx.x * blockDim.x + threadIdx.x; i < N; i += gridDim.x * blockDim.x) {
        m1 = fmaxf(m1, fabsf(sw1[i]));
        m2 = fmaxf(m2, fabsf(sw2[i]));
    }
#pragma unroll
    for (int o = 16; o > 0; o >>= 1) {
        m1 = fmaxf(m1, __shfl_xor_sync(0xFFFFFFFF, m1, o));
        m2 = fmaxf(m2, __shfl_xor_sync(0xFFFFFFFF, m2, o));
    }
    if ((threadIdx.x & 31) == 0) {
        atomicMax(&g_absmax[0], __float_as_int(m1));
        atomicMax(&g_absmax[1], __float_as_int(m2));
    }
}

// ------------------------- fused weight prep --------------------------------
__global__ void prep(const float* __restrict__ sw1, const float* __restrict__ bw1,
                     const float* __restrict__ sw2, const float* __restrict__ bw2) {
    unsigned gi = blockIdx.x * blockDim.x + threadIdx.x;
    if (gi < W1ELEMS) {
        unsigned idx = gi;
        unsigned r = idx & 1, lane = (idx >> 1) & 31;
        unsigned nt = (idx >> 6) % 48, ks = (idx >> 6) / 48;
        unsigned n = nt * 8 + (lane >> 2);
        unsigned k = ks * 16 + r * 8 + (lane & 3) * 2;
        float v0 = 0.0f, v1 = 0.0f;
        if (k < 1568)       v0 = sw1[n * 1568 + k];
        else if (k < 1764)  v0 = bw1[n * 196 + (k - 1568)];
        unsigned k1 = k + 1;
        if (k1 < 1568)      v1 = sw1[n * 1568 + k1];
        else if (k1 < 1764) v1 = bw1[n * 196 + (k1 - 1568)];
        g_W1[idx] = h2pack(v0, v1);
    } else if (gi < W1ELEMS + W2ELEMS) {
        unsigned idx = gi - W1ELEMS;
        unsigned r = idx & 1, lane = (idx >> 1) & 31;
        unsigned nt = (idx >> 6) % 25, ks = (idx >> 6) / 25;
        unsigned n = nt * 8 + (lane >> 2);
        unsigned k = ks * 16 + r * 8 + (lane & 3) * 2;
        float v0 = 0.0f, v1 = 0.0f;
        if (n < PP) {
            if (k < 3072)       v0 = sw2[n * 3072 + k];
            else                v0 = bw2[n * 384 + (k - 3072)];
            unsigned k1 = k + 1;
            if (k1 < 3072)      v1 = sw2[n * 3072 + k1];
            else                v1 = bw2[n * 384 + (k1 - 3072)];
        }
        g_W2[idx] = h2pack(v0, v1);
    } else if (gi < W1ELEMS + W2ELEMS + Q1ELEMS) {
        unsigned idx = gi - (W1ELEMS + W2ELEMS);
        unsigned r = idx & 1, lane = (idx >> 1) & 31;
        unsigned nt = (idx >> 6) % 48, kc = (idx >> 6) / 48;
        unsigned n = nt * 8 + (lane >> 2);
        unsigned kb = kc * 32 + (lane & 3) * 4 + r * 16;
        float inv = 127.0f / __int_as_float(g_absmax[0]);
        int q[4];
#pragma unroll
        for (int j = 0; j < 4; ++j) {
            float v = sw1[n * 1568 + kb + j] * inv;
            q[j] = __float2int_rn(fminf(fmaxf(v, -127.0f), 127.0f));
        }
        g_W1q[idx] = pack4(q[0], q[1], q[2], q[3]);
    } else if (gi < W1ELEMS + W2ELEMS + Q1ELEMS + Q2ELEMS) {
        unsigned idx = gi - (W1ELEMS + W2ELEMS + Q1ELEMS);
        unsigned r = idx & 1, lane = (idx >> 1) & 31;
        unsigned nt = (idx >> 6) % 25, kc = (idx >> 6) / 25;
        unsigned n = nt * 8 + (lane >> 2);
        unsigned kb = kc * 32 + (lane & 3) * 4 + r * 16;
        unsigned pk = 0;
        if (n < PP) {
            float inv = 127.0f / __int_as_float(g_absmax[1]);
            int q[4];
#pragma unroll
            for (int j = 0; j < 4; ++j) {
                float v = sw2[n * 3072 + kb + j] * inv;
                q[j] = __float2int_rn(fminf(fmaxf(v, -127.0f), 127.0f));
            }
            pk = pack4(q[0], q[1], q[2], q[3]);
        }
        g_W2q[idx] = pk;
    }
}

// ------------------------------ main kernel ---------------------------------
#define SM_B1   0
#define SM_B2   384
#define SM_R0   640
#define SM_A0   13184
#define SM_A1   14208
#define SM_BS0  15232
#define SM_BS1  21376
#define SM_TOTF 27520
#define HST     392        // h stride in halfs

__global__ void __launch_bounds__(NTH, 2)
kan_main(const float* __restrict__ x, const float* __restrict__ b1,
         const float* __restrict__ b2, float* __restrict__ out) {
    extern __shared__ float smem[];
    float*  b1s = smem + SM_B1;
    float*  b2s = smem + SM_B2;
    float*  xs  = smem + SM_R0;                              // fp32 [196][64]
    __half* hs  = reinterpret_cast<__half*>(smem + SM_R0);   // fp16 [64][392]
    unsigned* Bsu[2] = { reinterpret_cast<unsigned*>(smem + SM_BS0),
                         reinterpret_cast<unsigned*>(smem + SM_BS1) };
    uint4* As4[2] = { reinterpret_cast<uint4*>(smem + SM_A0),
                      reinterpret_cast<uint4*>(smem + SM_A1) };
    uint2* As2[2] = { reinterpret_cast<uint2*>(smem + SM_A0),
                      reinterpret_cast<uint2*>(smem + SM_A1) };

    const int tid = threadIdx.x;
    const int w = tid >> 5, lane = tid & 31;
    const int mw = w & 1;           // row half
    const int nG = w >> 1;          // col group 0..3
    const int g = lane >> 2, c4 = lane & 3;
    const int nt2_base = (nG == 0) ? 0 : (1 + 6 * nG);   // 0,7,13,19
    const int nt2_cnt  = (nG == 0) ? 7 : 6;
    // fp16 gen decomposition (per-thread uint4 fragment)
    const int fmt = tid >> 6, fks = (tid >> 5) & 1;
    const int fc4 = c4;
    const int fr0 = fmt * 16 + g, fr1 = fr0 + 8;
    // s8 gen decomposition (per-thread uint2 = half fragment)
    const int qfh  = tid & 1;            // k half (+16)
    const int qfno = tid >> 1;           // fragment 0..127
    const int qlf  = qfno & 31, qmt = qfno >> 5;
    const int qg = qlf >> 2, qc4 = qlf & 3;
    const int qR0 = qmt * 16 + qg;       // rows qR0, qR0+8
    const int qpo = (qc4 >> 1) + qfh * 2;        // patch offset within chunk (0..3)
    const float qq0 = (float)((qc4 & 1) * 4);    // first grid index of the quad

    const int m0 = blockIdx.x * MTILE;
    const int b  = m0 / CC;
    const int c0 = m0 % CC;

    const float factor1 = __int_as_float(g_absmax[0]) * (1.0f / 16129.0f);
    const float factor2 = __int_as_float(g_absmax[1]) * (1.0f / 16129.0f);

    // quantized basis quad: 4 features of one value at grids q0..q0+3
    auto bquad = [&](float xv) -> unsigned {
        float d  = fmaf(xv, 3.5f, 3.5f - qq0);
        float z0 = -d * d * L2E;
        float t  = fmaf(2.0f * L2E, d, -L2E);
        float z1 = z0 + t; t -= 2.0f * L2E;
        float z2 = z1 + t; t -= 2.0f * L2E;
        float z3 = z2 + t;
        int i0 = __float2int_rn(ex2f(fmaxf(z0, -126.0f)) * 127.0f);
        int i1 = __float2int_rn(ex2f(fmaxf(z1, -126.0f)) * 127.0f);
        int i2 = __float2int_rn(ex2f(fmaxf(z2, -126.0f)) * 127.0f);
        int i3 = __float2int_rn(ex2f(fmaxf(z3, -126.0f)) * 127.0f);
        return pack4(i0, i1, i2, i3);
    };

    // ---- s8 A generators (one uint2 per thread) ----
    auto genA1q = [&](int kc, uint2* dst) {
        const int p = kc * 4 + qpo;
        uint2 aw;
        aw.x = bquad(xs[p * 64 + qR0]);
        aw.y = bquad(xs[p * 64 + qR0 + 8]);
        dst[tid] = aw;
    };
    auto genA2q = [&](int kc, uint2* dst) {
        const int j = kc * 4 + qpo;
        uint2 aw;
        aw.x = bquad(__half2float(hs[qR0 * HST + j]));
        aw.y = bquad(__half2float(hs[(qR0 + 8) * HST + j]));
        dst[tid] = aw;
    };

    // ---- fp16 A generators (base region; one uint4 per thread) ----
    auto genA1f = [&](int kc, uint4* dst) {
        const int kb0 = kc * 32 + fks * 16 + fc4 * 2;
        const int kb1 = kb0 + 8;
        uint4 aw;
        float f00 = (kb0 < 1764) ? silu_feat(xs[(kb0 - 1568) * 64 + fr0]) : 0.0f;
        float f01 = (kb0 + 1 < 1764) ? silu_feat(xs[(kb0 - 1567) * 64 + fr0]) : 0.0f;
        float f02 = (kb0 < 1764) ? silu_feat(xs[(kb0 - 1568) * 64 + fr1]) : 0.0f;
        float f03 = (kb0 + 1 < 1764) ? silu_feat(xs[(kb0 - 1567) * 64 + fr1]) : 0.0f;
        float f10 = (kb1 < 1764) ? silu_feat(xs[(kb1 - 1568) * 64 + fr0]) : 0.0f;
        float f11 = (kb1 + 1 < 1764) ? silu_feat(xs[(kb1 - 1567) * 64 + fr0]) : 0.0f;
        float f12 = (kb1 < 1764) ? silu_feat(xs[(kb1 - 1568) * 64 + fr1]) : 0.0f;
        float f13 = (kb1 + 1 < 1764) ? silu_feat(xs[(kb1 - 1567) * 64 + fr1]) : 0.0f;
        aw.x = h2pack(f00, f01);
        aw.y = h2pack(f02, f03);
        aw.z = h2pack(f10, f11);
        aw.w = h2pack(f12, f13);
        dst[tid] = aw;
    };
    auto genA2f = [&](int kc, uint4* dst) {
        const int kb0 = kc * 32 + fks * 16 + fc4 * 2;
        const int kb1 = kb0 + 8;
        const int j00 = kb0 - 3072, j10 = kb1 - 3072;
        uint4 aw;
        aw.x = h2pack(silu_feat(__half2float(hs[fr0 * HST + j00])),
                      silu_feat(__half2float(hs[fr0 * HST + j00 + 1])));
        aw.y = h2pack(silu_feat(__half2float(hs[fr1 * HST + j00])),
                      silu_feat(__half2float(hs[fr1 * HST + j00 + 1])));
        aw.z = h2pack(silu_feat(__half2float(hs[fr0 * HST + j10])),
                      silu_feat(__half2float(hs[fr0 * HST + j10 + 1])));
        aw.w = h2pack(silu_feat(__half2float(hs[fr1 * HST + j10])),
                      silu_feat(__half2float(hs[fr1 * HST + j10 + 1])));
        dst[tid] = aw;
    };

    // ---- weight staging ----
    auto prefW1f = [&](int kc, int bi) {            // fp16 chunk: 6144 uints
        const unsigned* src = g_W1 + (size_t)kc * 6144;
        unsigned* dst = Bsu[bi];
#pragma unroll
        for (int i = 0; i < 6; ++i) {
            int v = tid + i * NTH;
            cpasync16(dst + v * 4, src + (size_t)v * 4);
        }
        cp_commit();
    };
    auto prefW2f = [&](int kc, int bi) {            // fp16 chunk: 3200 uints
        const unsigned* src = g_W2 + (size_t)kc * L2CHUNK;
        unsigned* dst = Bsu[bi];
#pragma unroll
        for (int i = 0; i < 3; ++i) {
            int v = tid + i * NTH;
            cpasync16(dst + v * 4, src + (size_t)v * 4);
        }
        if (tid < 32) cpasync16(dst + (768 + tid) * 4, src + (size_t)(768 + tid) * 4);
        cp_commit();
    };
    auto prefW1q = [&](int kc, int bi) {            // s8 chunk: 3072 uints
        const unsigned* src = g_W1q + (size_t)kc * 3072;
        unsigned* dst = Bsu[bi];
#pragma unroll
        for (int i = 0; i < 3; ++i) {
            int v = tid + i * NTH;
            cpasync16(dst + v * 4, src + (size_t)v * 4);
        }
        cp_commit();
    };
    auto prefW2q = [&](int kc, int bi) {            // s8 chunk: 1600 uints
        const unsigned* src = g_W2q + (size_t)kc * 1600;
        unsigned* dst = Bsu[bi];
#pragma unroll
        for (int i = 0; i < 2; ++i) {
            int v = tid + i * NTH;
            if (v < 400) cpasync16(dst + v * 4, src + (size_t)v * 4);
        }
        cp_commit();
    };

    // ---- prefetch L1 s8 chunk 0 ----
    prefW1q(0, 0);

    // ---- load x slab + biases ----
    {
        const float4* xg = reinterpret_cast<const float4*>(x + (size_t)b * PP * CC + c0);
        float4* xs4 = reinterpret_cast<float4*>(xs);
        for (int i = tid; i < PP * 16; i += NTH) {
            int p = i >> 4, r4 = i & 15;
            xs4[p * 16 + r4] = xg[p * (CC / 4) + r4];
        }
        for (int i = tid; i < HSZ; i += NTH) b1s[i] = b1[i];
        if (tid < 200) b2s[tid] = (tid < PP) ? b2[tid] : 0.0f;
    }
    __syncthreads();

    // ============================ layer 1 ============================
    {
        float acc[2][12][4];

        // ---- spline region: int8 k32 MMAs ----
        {
            int sacc[2][12][4] = {};
            genA1q(0, As2[0]);
            for (int kc = 0; kc < 49; ++kc) {
                const int bi = kc & 1;
                cp_wait0();
                __syncthreads();
                if (kc + 1 < 49) {
                    prefW1q(kc + 1, bi ^ 1);
                    genA1q(kc + 1, As2[bi ^ 1]);
                } else {
                    prefW1f(49, bi ^ 1);            // transition to fp16 base
                    genA1f(49, As4[bi ^ 1]);
                }
                const uint2* Bs2 = reinterpret_cast<const uint2*>(Bsu[bi]);
                uint4 Af[2];
#pragma unroll
                for (int mi = 0; mi < 2; ++mi)
                    Af[mi] = As4[bi][(mw * 2 + mi) * 32 + lane];
#pragma unroll
                for (int nti = 0; nti < 12; ++nti) {
                    int nt = nG * 12 + nti;
                    uint2 Bf = Bs2[nt * 32 + lane];
#pragma unroll
                    for (int mi = 0; mi < 2; ++mi) mmas8(sacc[mi][nti], Af[mi], Bf);
                }
            }
            // dequant merge s32 -> f32
#pragma unroll
            for (int mi = 0; mi < 2; ++mi)
#pragma unroll
                for (int nti = 0; nti < 12; ++nti)
#pragma unroll
                    for (int ci = 0; ci < 4; ++ci)
                        acc[mi][nti][ci] = (float)sacc[mi][nti][ci] * factor1;
        }

        // ---- base region: fp16 MMAs, fp32 acc ----
        for (int kc = 49; kc < NC1; ++kc) {
            const int bi = kc & 1;
            cp_wait0();
            __syncthreads();
            if (kc + 1 < NC1) {
                prefW1f(kc + 1, bi ^ 1);
                genA1f(kc + 1, As4[bi ^ 1]);
            } else {
                prefW2q(0, 0);                      // kc=55 (bi=1) -> L2 s8 chunk 0
            }
            const uint2* Bs2 = reinterpret_cast<const uint2*>(Bsu[bi]);
#pragma unroll
            for (int ks = 0; ks < 2; ++ks) {
                uint4 Af[2];
#pragma unroll
                for (int mi = 0; mi < 2; ++mi)
                    Af[mi] = As4[bi][((mw * 2 + mi) * 2 + ks) * 32 + lane];
#pragma unroll
                for (int nti = 0; nti < 12; ++nti) {
                    int nt = nG * 12 + nti;
                    uint2 Bf = Bs2[(ks * NT1 + nt) * 32 + lane];
#pragma unroll
                    for (int mi = 0; mi < 2; ++mi) mma16(acc[mi][nti], Af[mi], Bf);
                }
            }
        }

        __syncthreads();   // all xs reads done before hs overwrite

        // ---- h epilogue: hs[row][col] = fp16(acc + b1[col]) ----
#pragma unroll
        for (int mi = 0; mi < 2; ++mi)
#pragma unroll
            for (int nti = 0; nti < 12; ++nti)
#pragma unroll
                for (int ci = 0; ci < 4; ++ci) {
                    int row = mw * 32 + mi * 16 + g + 8 * (ci >> 1);
                    int col = nG * 96 + nti * 8 + 2 * c4 + (ci & 1);
                    hs[row * HST + col] = __float2half(acc[mi][nti][ci] + b1s[col]);
                }
    }
    __syncthreads();       // hs visible to all

    // ============================ layer 2 ============================
    {
        float acc[2][7][4];

        // ---- spline region: int8 k32 MMAs ----
        {
            int sacc[2][7][4] = {};
            genA2q(0, As2[0]);
            for (int kc = 0; kc < 96; ++kc) {
                const int bi = kc & 1;
                cp_wait0();
                __syncthreads();
                if (kc + 1 < 96) {
                    prefW2q(kc + 1, bi ^ 1);
                    genA2q(kc + 1, As2[bi ^ 1]);
                } else {
                    prefW2f(96, bi ^ 1);            // transition to fp16 base
                    genA2f(96, As4[bi ^ 1]);
                }
                const uint2* Bs2 = reinterpret_cast<const uint2*>(Bsu[bi]);
                uint4 Af[2];
#pragma unroll
                for (int mi = 0; mi < 2; ++mi)
                    Af[mi] = As4[bi][(mw * 2 + mi) * 32 + lane];
#pragma unroll
                for (int nti = 0; nti < 7; ++nti) {
                    if (nti < nt2_cnt) {
                        int nt = nt2_base + nti;
                        uint2 Bf = Bs2[nt * 32 + lane];
#pragma unroll
                        for (int mi = 0; mi < 2; ++mi) mmas8(sacc[mi][nti], Af[mi], Bf);
                    }
                }
            }
#pragma unroll
            for (int mi = 0; mi < 2; ++mi)
#pragma unroll
                for (int nti = 0; nti < 7; ++nti)
#pragma unroll
                    for (int ci = 0; ci < 4; ++ci)
                        acc[mi][nti][ci] = (float)sacc[mi][nti][ci] * factor2;
        }

        // ---- base region: fp16 MMAs, fp32 acc ----
        for (int kc = 96; kc < NC2; ++kc) {
            const int bi = kc & 1;
            cp_wait0();
            __syncthreads();
            if (kc + 1 < NC2) {
                prefW2f(kc + 1, bi ^ 1);
                genA2f(kc + 1, As4[bi ^ 1]);
            }
            const uint2* Bs2 = reinterpret_cast<const uint2*>(Bsu[bi]);
#pragma unroll
            for (int ks = 0; ks < 2; ++ks) {
                uint4 Af[2];
#pragma unroll
                for (int mi = 0; mi < 2; ++mi)
                    Af[mi] = As4[bi][((mw * 2 + mi) * 2 + ks) * 32 + lane];
#pragma unroll
                for (int nti = 0; nti < 7; ++nti) {
                    if (nti < nt2_cnt) {
                        int nt = nt2_base + nti;
                        uint2 Bf = Bs2[(ks * NT2 + nt) * 32 + lane];
#pragma unroll
                        for (int mi = 0; mi < 2; ++mi) mma16(acc[mi][nti], Af[mi], Bf);
                    }
                }
            }
        }

        // ---- epilogue: out = acc + b2[p] + x ----
#pragma unroll
        for (int mi = 0; mi < 2; ++mi)
#pragma unroll
            for (int nti = 0; nti < 7; ++nti) {
                if (nti < nt2_cnt) {
#pragma unroll
                    for (int ci = 0; ci < 4; ++ci) {
                        int row = mw * 32 + mi * 16 + g + 8 * (ci >> 1);
                        int p   = (nt2_base + nti) * 8 + 2 * c4 + (ci & 1);
                        if (p < PP) {
                            size_t ga = ((size_t)b * PP + p) * CC + c0 + row;
                            out[ga] = acc[mi][nti][ci] + b2s[p] + x[ga];
                        }
                    }
                }
            }
    }
}

// ------------------------------ launcher ------------------------------------
extern "C" void kernel_launch(void* const* d_in, const int* in_sizes, int n_in,
                              void* d_out, int out_size) {
    (void)in_sizes; (void)n_in; (void)out_size;
    const float* x  = (const float*)d_in[0];
    const float* s1 = (const float*)d_in[1];
    const float* w1 = (const float*)d_in[2];
    const float* b1 = (const float*)d_in[3];
    const float* s2 = (const float*)d_in[4];
    const float* w2 = (const float*)d_in[5];
    const float* b2 = (const float*)d_in[6];
    float* out = (float*)d_out;

    absmax_k<<<148, 256>>>(s1, s2);
    const unsigned PREP_TOT = W1ELEMS + W2ELEMS + Q1ELEMS + Q2ELEMS;
    prep<<<(PREP_TOT + 255) / 256, 256>>>(s1, w1, s2, w2);

    const int smemBytes = SM_TOTF * 4;   // 110,080 B -> 2 CTAs/SM
    cudaFuncSetAttribute(kan_main, cudaFuncAttributeMaxDynamicSharedMemorySize, smemBytes);
    kan_main<<<(64 * CC) / MTILE, NTH, smemBytes>>>(x, b1, b2, out);
}